// round 7
// baseline (speedup 1.0000x reference)
#include <cuda_runtime.h>
#include <cuda_bf16.h>

// LeakyAvg: out[b,h,t,d] = sum_{s<=t} exp(-beta_h*(t-s)) * k[b,h,s,d]
//  == linear recurrence y[t] = a*y[t-1] + k[t], a = exp(-beta_h) <= e^-0.5.
// a^32 <= e^-16 ~ 1.1e-7 rel: chunks computed independently with a 32-step
// warm-up are numerically identical to the exact scan (measured 2.4e-8).
//
// Evidence so far:
//  R3 CHUNK=128: occ 10%, 14.4us.  R5 CHUNK=32: occ 37%, 12.3us.
//  R6 CHUNK=16: occ 66%, 13.0us (WORSE).  DRAM pinned ~28% all rounds,
//  working set is L2-resident -> binding resource is LTS throughput
//  (~6300 B/cyc cap; R6 ran ~75% of it).  Lever = cut L2 traffic.
//
// R7: smem halo tiling. Block = 8 warps stages 160 rows (128 emit + 32 halo,
// 40 KB) of one (b,h) into smem ONCE (L2 read amp 1.25x vs 3x), then warp w
// scans 48 steps (32 warm + 16 emit) from smem. t<0 halo is zero-filled,
// which equals the true initial condition, so all warps are uniform.

namespace {
constexpr int NH   = 16;
constexpr int T    = 2048;
constexpr int HS   = 64;
constexpr int WARM = 32;
constexpr int WARPS = 8;
constexpr int CHUNK = 16;                 // emit steps per warp
constexpr int SEG   = WARPS * CHUNK;      // 128 emit steps per block
constexpr int ROWS  = SEG + WARM;         // 160 staged rows
constexpr int THREADS = 32 * WARPS;       // 256
constexpr int F4_PER_ROW = HS / 4;        // 16
constexpr int F4_TOTAL   = ROWS * F4_PER_ROW;          // 2560
constexpr int F4_PER_THR = F4_TOTAL / THREADS;         // 10
}

__global__ __launch_bounds__(THREADS)
void leaky_avg_scan_kernel(const float* __restrict__ k,
                           const float* __restrict__ lkb,
                           float* __restrict__ out)
{
    __shared__ float sk[ROWS * HS];       // 40 KB

    const int seg = blockIdx.x;           // 0 .. T/SEG-1
    const int h   = blockIdx.y;
    const int b   = blockIdx.z;
    const int tid = threadIdx.x;

    const float beta = fabsf(lkb[h]) * 10.0f;
    const float a = expf(-beta);

    const int t0 = seg * SEG;
    const long gbase = (long)t0 - WARM;   // -32 for seg 0
    const size_t rowbase = ((size_t)(b * NH + h)) * T;

    // ── Cooperative staging: smem row i <-> global timestep gbase+i ──
    {
        const float4* src = reinterpret_cast<const float4*>(k + rowbase * HS);
        float4* s4 = reinterpret_cast<float4*>(sk);
        const long goff = gbase * F4_PER_ROW;   // float4 offset of smem origin
        #pragma unroll
        for (int i = 0; i < F4_PER_THR; ++i) {
            const int e = tid + i * THREADS;    // 0 .. 2559
            float4 v = make_float4(0.f, 0.f, 0.f, 0.f);
            if (goff + e >= 0)                  // t < 0 halo -> zeros
                v = src[goff + e];
            s4[e] = v;
        }
    }
    __syncthreads();

    // ── Per-warp scan out of smem ──
    const int warp = tid >> 5;
    const int lane = tid & 31;
    constexpr int STRIDE2 = HS / 2;             // float2 per row

    // Warp w: warm-up over smem rows [16w, 16w+32), emit rows [16w+32, 16w+48)
    const float2* sp = reinterpret_cast<const float2*>(sk)
                       + (warp * CHUNK) * STRIDE2 + lane;
    float2* op = reinterpret_cast<float2*>(out + (rowbase + t0 + warp * CHUNK) * HS)
                 + lane;

    float2 y = make_float2(0.0f, 0.0f);
    #pragma unroll
    for (int j = 0; j < WARM + CHUNK; ++j) {
        float2 kv = sp[j * STRIDE2];
        y.x = fmaf(a, y.x, kv.x);
        y.y = fmaf(a, y.y, kv.y);
        if (j >= WARM)
            op[(j - WARM) * STRIDE2] = y;
    }
}

extern "C" void kernel_launch(void* const* d_in, const int* in_sizes, int n_in,
                              void* d_out, int out_size)
{
    const float* k   = (const float*)d_in[0];
    const float* lkb = (const float*)d_in[1];
    float* out = (float*)d_out;

    const int B = in_sizes[0] / (NH * T * HS);   // 4 for this problem

    dim3 grid(T / SEG, NH, B);                   // (16, 16, 4) = 1024 blocks
    dim3 block(THREADS);                         // 256 threads
    leaky_avg_scan_kernel<<<grid, block>>>(k, lkb, out);
}

// round 8
// speedup vs baseline: 1.0538x; 1.0538x over previous
#include <cuda_runtime.h>
#include <cuda_bf16.h>

// LeakyAvg: out[b,h,t,d] = sum_{s<=t} exp(-beta_h*(t-s)) * k[b,h,s,d]
//  == linear recurrence y[t] = a*y[t-1] + k[t], a = exp(-beta_h) <= e^-0.5.
// a^32 <= e^-16: chunks computed independently with a 32-step warm-up are
// numerically identical to the exact scan (measured rel_err 2.4e-8).
//
// Evidence R3-R7: occ 10->66%, L2 traffic +-35%, smem staging -- duration
// pinned at 12.3-15us with every ncu ceiling < 42%. Conclusion: bound by
// per-SM outstanding-load capacity x latency (queue-depth bound), not by
// occupancy, issue, L2 or DRAM. Lever: 2x bytes per in-flight load.
//
// R8: HALF-WARP streams with float4 lanes. Lanes 0-15 scan chunk c, lanes
// 16-31 scan chunk c+1; each lane owns 4 dims. One LDG.128 = one full row
// for BOTH streams (2 x 256B contiguous segments = 4 sectors, same cost as
// a contiguous 512B load). Halves LDG and STG instruction counts, doubles
// bytes-in-flight at the same queue depth. No cross-lane communication.

namespace {
constexpr int NH   = 16;
constexpr int T    = 2048;
constexpr int HS   = 64;
constexpr int CHUNK = 16;            // emitted timesteps per half-warp
constexpr int WARM  = 32;            // warm-up timesteps (discarded)
constexpr int WARPS_PER_BLOCK = 4;   // 8 adjacent chunks per block
constexpr int STREAMS_PER_BLOCK = WARPS_PER_BLOCK * 2;
constexpr int F4_PER_ROW = HS / 4;   // 16 float4 per timestep row
}

__global__ __launch_bounds__(32 * WARPS_PER_BLOCK)
void leaky_avg_scan_kernel(const float* __restrict__ k,
                           const float* __restrict__ lkb,
                           float* __restrict__ out)
{
    const int tid  = threadIdx.x;
    const int sub  = tid & 15;                       // lane within half-warp
    const int hw   = tid >> 4;                       // half-warp id in block
    const int chunk = blockIdx.x * STREAMS_PER_BLOCK + hw;  // 0 .. T/CHUNK-1
    const int h    = blockIdx.y;
    const int b    = blockIdx.z;

    const float beta = fabsf(lkb[h]) * 10.0f;
    const float a = expf(-beta);

    const int t0 = chunk * CHUNK;
    const int ts = (t0 >= WARM) ? (t0 - WARM) : 0;
    const int nwarm = t0 - ts;                       // 0, 16, or 32

    const size_t rowbase = ((size_t)(b * NH + h)) * T;

    // float4 view: element index = (rowbase + t) * F4_PER_ROW + sub
    const float4* kp = reinterpret_cast<const float4*>(k)
                       + (rowbase + ts) * F4_PER_ROW + sub;

    float4 y = make_float4(0.f, 0.f, 0.f, 0.f);

    // Warm-up: establish state at t0-1 (exact to fp32; tail < e^-16).
    #pragma unroll 8
    for (int i = 0; i < nwarm; ++i) {
        float4 v = kp[i * F4_PER_ROW];
        y.x = fmaf(a, y.x, v.x);
        y.y = fmaf(a, y.y, v.y);
        y.z = fmaf(a, y.z, v.z);
        y.w = fmaf(a, y.w, v.w);
    }

    const float4* ep = reinterpret_cast<const float4*>(k)
                       + (rowbase + t0) * F4_PER_ROW + sub;
    float4* op = reinterpret_cast<float4*>(out)
                 + (rowbase + t0) * F4_PER_ROW + sub;

    // Emit loop: fully unrolled, loads independent of y -> front-batched.
    #pragma unroll
    for (int i = 0; i < CHUNK; ++i) {
        float4 v = ep[i * F4_PER_ROW];
        y.x = fmaf(a, y.x, v.x);
        y.y = fmaf(a, y.y, v.y);
        y.z = fmaf(a, y.z, v.z);
        y.w = fmaf(a, y.w, v.w);
        op[i * F4_PER_ROW] = y;
    }
}

extern "C" void kernel_launch(void* const* d_in, const int* in_sizes, int n_in,
                              void* d_out, int out_size)
{
    const float* k   = (const float*)d_in[0];
    const float* lkb = (const float*)d_in[1];
    float* out = (float*)d_out;

    const int B = in_sizes[0] / (NH * T * HS);   // 4 for this problem

    // chunks per (b,h) = T/CHUNK = 128; 8 streams per block
    dim3 grid((T / CHUNK) / STREAMS_PER_BLOCK, NH, B);  // (16, 16, 4)
    dim3 block(32 * WARPS_PER_BLOCK);                   // 128 threads
    leaky_avg_scan_kernel<<<grid, block>>>(k, lkb, out);
}